// round 1
// baseline (speedup 1.0000x reference)
#include <cuda_runtime.h>

#define Bsz 8
#define Ccls 5
#define Hh 512
#define Ww 512
#define HW 262144      // 512*512
#define BHW 2097152    // 8*HW
#define CF 32
#define Dd 256
#define FG 1
#define MAXT 1024
#define MAXO 4096
#define NSCAN 2048     // scan blocks, 1024 px each

// ---------------- scratch (no allocations allowed) ----------------
__device__ double g_acc[18];        // 0 ce,1 focal,2..6 probsum,7..11 inter,12..16 cnt,17 grad
__device__ double g_tinySum;
__device__ float  g_cls;
__device__ float  g_predfg[BHW];
__device__ int    g_blockcnt[NSCAN];
__device__ int    g_blockpref[NSCAN];
__device__ int    g_flags[Bsz];
__device__ int    g_nT, g_nO, g_enabled;
__device__ int    g_tinyIdx[MAXT];
__device__ int    g_otherIdx[MAXO];
__device__ float  g_cols[(MAXT + MAXO) * CF];   // [col][32] row-major, cols: 0..1023 tiny, 1024..5119 other
__device__ float4 g_part[MAXT * 8];             // per (row, chunk): {mT,sT,mO,sO}

// ---------------- helpers ----------------
__device__ __forceinline__ void lseUpd(float& m, float& s, float v) {
    if (v > m) { s = s * expf(m - v) + 1.0f; m = v; }
    else       { s += expf(v - m); }
}
__device__ __forceinline__ void lseMerge(float& m, float& s, float m2, float s2) {
    if (s2 > 0.0f) {
        if (m2 > m) { s = s * expf(m - m2) + s2; m = m2; }
        else        { s += s2 * expf(m2 - m); }
    }
}
#define WSUM(v) { _Pragma("unroll") for (int _o = 16; _o; _o >>= 1) v += __shfl_xor_sync(0xffffffffu, v, _o); }

// ---------------- init ----------------
__global__ void k_init() {
    int t = threadIdx.x;
    if (t < 18) g_acc[t] = 0.0;
    if (t == 18) g_tinySum = 0.0;
}

// ---------------- pass 1: softmax stats (CE, focal, dice pieces, pred_fg, fg block counts) ----------------
__global__ __launch_bounds__(256) void k_stats(const float* __restrict__ logits,
                                               const int* __restrict__ tgt) {
    int base = blockIdx.x * 1024 + threadIdx.x;      // block covers 1024 px, all inside one image
    int b = (blockIdx.x * 1024) >> 18;
    const float* lb = logits + (size_t)b * Ccls * HW;

    float ceA = 0.f, foA = 0.f;
    float p0 = 0.f, p1 = 0.f, p2 = 0.f, p3 = 0.f, p4 = 0.f;
    float i0 = 0.f, i1 = 0.f, i2 = 0.f, i3 = 0.f, i4 = 0.f;
    float c0 = 0.f, c1 = 0.f, c2 = 0.f, c3 = 0.f, c4 = 0.f;

#pragma unroll
    for (int i = 0; i < 4; i++) {
        int p = base + i * 256;
        int hw = p & (HW - 1);
        float x0 = lb[hw], x1 = lb[HW + hw], x2 = lb[2 * HW + hw],
              x3 = lb[3 * HW + hw], x4 = lb[4 * HW + hw];
        float m = fmaxf(fmaxf(fmaxf(x0, x1), fmaxf(x2, x3)), x4);
        float e0 = expf(x0 - m), e1 = expf(x1 - m), e2 = expf(x2 - m),
              e3 = expf(x3 - m), e4 = expf(x4 - m);
        float S = e0 + e1 + e2 + e3 + e4;
        float logS = logf(S);
        float inv = 1.0f / S;
        int t = tgt[p];
        float xt = (t == 0) ? x0 : (t == 1) ? x1 : (t == 2) ? x2 : (t == 3) ? x3 : x4;
        float ce = -(xt - m - logS);
        float pt = expf(-ce);
        float om = fminf(fmaxf(1.0f - pt, 0.0f), 1.0f);
        ceA += ce;
        foA += om * om * ce;
        p0 += e0 * inv; p1 += e1 * inv; p2 += e2 * inv; p3 += e3 * inv; p4 += e4 * inv;
        i0 += (t == 0) ? pt : 0.f; i1 += (t == 1) ? pt : 0.f; i2 += (t == 2) ? pt : 0.f;
        i3 += (t == 3) ? pt : 0.f; i4 += (t == 4) ? pt : 0.f;
        c0 += (t == 0) ? 1.f : 0.f; c1 += (t == 1) ? 1.f : 0.f; c2 += (t == 2) ? 1.f : 0.f;
        c3 += (t == 3) ? 1.f : 0.f; c4 += (t == 4) ? 1.f : 0.f;
        g_predfg[p] = e1 * inv;
    }

    __shared__ float sa[17];
    if (threadIdx.x < 17) sa[threadIdx.x] = 0.f;
    __syncthreads();
    int lane = threadIdx.x & 31;
    WSUM(ceA) WSUM(foA)
    WSUM(p0) WSUM(p1) WSUM(p2) WSUM(p3) WSUM(p4)
    WSUM(i0) WSUM(i1) WSUM(i2) WSUM(i3) WSUM(i4)
    WSUM(c0) WSUM(c1) WSUM(c2) WSUM(c3) WSUM(c4)
    if (lane == 0) {
        atomicAdd(&sa[0], ceA); atomicAdd(&sa[1], foA);
        atomicAdd(&sa[2], p0); atomicAdd(&sa[3], p1); atomicAdd(&sa[4], p2);
        atomicAdd(&sa[5], p3); atomicAdd(&sa[6], p4);
        atomicAdd(&sa[7], i0); atomicAdd(&sa[8], i1); atomicAdd(&sa[9], i2);
        atomicAdd(&sa[10], i3); atomicAdd(&sa[11], i4);
        atomicAdd(&sa[12], c0); atomicAdd(&sa[13], c1); atomicAdd(&sa[14], c2);
        atomicAdd(&sa[15], c3); atomicAdd(&sa[16], c4);
    }
    __syncthreads();
    if (threadIdx.x < 17) atomicAdd(&g_acc[threadIdx.x], (double)sa[threadIdx.x]);
    if (threadIdx.x == 0) g_blockcnt[blockIdx.x] = (int)(sa[12 + FG] + 0.5f);
}

// ---------------- pass 2: sobel gradient loss ----------------
__global__ __launch_bounds__(256) void k_sobel(const int* __restrict__ tgt) {
    int p = blockIdx.x * 256 + threadIdx.x;
    int b = p >> 18;
    int hw = p & (HW - 1);
    int h = hw >> 9, w = hw & 511;
    const float* pf = g_predfg + b * HW;
    const int* tb = tgt + b * HW;

    float P[3][3], T[3][3];
#pragma unroll
    for (int dh = -1; dh <= 1; dh++)
#pragma unroll
        for (int dw = -1; dw <= 1; dw++) {
            int hh = h + dh, ww = w + dw;
            bool in = (hh >= 0) && (hh < Hh) && (ww >= 0) && (ww < Ww);
            int q = hh * Ww + ww;
            P[dh + 1][dw + 1] = in ? pf[q] : 0.0f;
            T[dh + 1][dw + 1] = in ? ((tb[q] > 0) ? 1.0f : 0.0f) : 0.0f;
        }
    float gxp = (P[0][2] + 2.f * P[1][2] + P[2][2]) - (P[0][0] + 2.f * P[1][0] + P[2][0]);
    float gyp = (P[2][0] + 2.f * P[2][1] + P[2][2]) - (P[0][0] + 2.f * P[0][1] + P[0][2]);
    float gxt = (T[0][2] + 2.f * T[1][2] + T[2][2]) - (T[0][0] + 2.f * T[1][0] + T[2][0]);
    float gyt = (T[2][0] + 2.f * T[2][1] + T[2][2]) - (T[0][0] + 2.f * T[0][1] + T[0][2]);
    float sp = sqrtf(gxp * gxp + gyp * gyp + 1e-6f);
    float st = sqrtf(gxt * gxt + gyt * gyt + 1e-6f);
    float d = fabsf(sp - st);

    __shared__ float sa;
    if (threadIdx.x == 0) sa = 0.f;
    __syncthreads();
    WSUM(d)
    if ((threadIdx.x & 31) == 0) atomicAdd(&sa, d);
    __syncthreads();
    if (threadIdx.x == 0) atomicAdd(&g_acc[17], (double)sa);
}

// ---------------- pass 3: tiny flags + exclusive scan over 2048 block counts ----------------
__global__ void k_scan() {
    __shared__ int simg[Bsz];
    __shared__ int flg[Bsz];
    __shared__ int sc[1024];
    int t = threadIdx.x;
    if (t < Bsz) simg[t] = 0;
    __syncthreads();
    int cA = g_blockcnt[2 * t], cB = g_blockcnt[2 * t + 1];
    int bA = (2 * t) >> 8, bB = (2 * t + 1) >> 8;
    atomicAdd(&simg[bA], cA);
    atomicAdd(&simg[bB], cB);
    __syncthreads();
    if (t < Bsz) flg[t] = (simg[t] > 0 && simg[t] <= 2048) ? 1 : 0;
    __syncthreads();
    int a0 = flg[bA] ? cA : 0;
    int a1 = flg[bB] ? cB : 0;
    sc[t] = a0 + a1;
    __syncthreads();
    for (int off = 1; off < 1024; off <<= 1) {
        int add = (t >= off) ? sc[t - off] : 0;
        __syncthreads();
        sc[t] += add;
        __syncthreads();
    }
    int incl = sc[t];
    int excl = incl - a0 - a1;
    g_blockpref[2 * t] = excl;
    g_blockpref[2 * t + 1] = excl + a0;
    if (t < Bsz) g_flags[t] = flg[t];
    if (t == 1023) {
        int tot = incl;
        int nT = tot < MAXT ? tot : MAXT;
        int oth = BHW - tot;
        g_nT = nT;
        g_nO = oth < MAXO ? oth : MAXO;
        int any = 0;
        for (int i = 0; i < Bsz; i++) any |= flg[i];
        g_enabled = (any && tot >= 16) ? 1 : 0;
    }
}

// ---------------- pass 4: ordered scatter of first-N indices ----------------
__global__ __launch_bounds__(256) void k_scatter(const int* __restrict__ tgt) {
    int sb = blockIdx.x;
    int prefT = g_blockpref[sb];
    int prefO = sb * 1024 - prefT;
    int nT = g_nT, nO = g_nO;
    if (prefT >= nT && prefO >= nO) return;   // uniform exit, before syncthreads
    int flag = g_flags[sb >> 8];
    int base = sb * 1024 + threadIdx.x * 4;
    int4 tv = *(const int4*)(tgt + base);
    int m0 = (tv.x == FG && flag) ? 1 : 0;
    int m1 = (tv.y == FG && flag) ? 1 : 0;
    int m2 = (tv.z == FG && flag) ? 1 : 0;
    int m3 = (tv.w == FG && flag) ? 1 : 0;
    int cnt = m0 + m1 + m2 + m3;

    __shared__ int s[256];
    s[threadIdx.x] = cnt;
    __syncthreads();
    for (int off = 1; off < 256; off <<= 1) {
        int add = (threadIdx.x >= off) ? s[threadIdx.x - off] : 0;
        __syncthreads();
        s[threadIdx.x] += add;
        __syncthreads();
    }
    int myExcl = s[threadIdx.x] - cnt;
    int tb = prefT + myExcl;
    int ob = prefO + threadIdx.x * 4 - myExcl;
    int p = base;
    if (m0) { if (tb < nT) g_tinyIdx[tb] = p; tb++; } else { if (ob < nO) g_otherIdx[ob] = p; ob++; }
    p = base + 1;
    if (m1) { if (tb < nT) g_tinyIdx[tb] = p; tb++; } else { if (ob < nO) g_otherIdx[ob] = p; ob++; }
    p = base + 2;
    if (m2) { if (tb < nT) g_tinyIdx[tb] = p; tb++; } else { if (ob < nO) g_otherIdx[ob] = p; ob++; }
    p = base + 3;
    if (m3) { if (tb < nT) g_tinyIdx[tb] = p; tb++; } else { if (ob < nO) g_otherIdx[ob] = p; ob++; }
}

// ---------------- pass 5: gather + l2-normalize feature rows ----------------
__global__ __launch_bounds__(256) void k_gather(const float* __restrict__ pf) {
    int r = blockIdx.x * 8 + (threadIdx.x >> 5);
    int lane = threadIdx.x & 31;
    int nT = g_nT, nO = g_nO;
    int idx = -1;
    if (r < MAXT) { if (r < nT) idx = g_tinyIdx[r]; }
    else { int j = r - MAXT; if (j < nO) idx = g_otherIdx[j]; }
    if (idx < 0) return;
    int b = idx >> 18;
    int hw = idx & (HW - 1);
    float v = pf[(size_t)(b * CF + lane) * HW + hw];
    float sq = v * v;
    WSUM(sq)
    float nrm = fmaxf(sqrtf(sq), 1e-12f);
    g_cols[r * CF + lane] = v / nrm;
}

// ---------------- pass 6: tiny contrastive — 1024x5120x32 dot + streaming LSE ----------------
// grid (64 row-blocks, 8 col-chunks). Block: 8 warps, 2 rows/warp -> 16 rows.
// Chunk: 640 cols = 5 tiles of 128.
__global__ __launch_bounds__(256) void k_tinyloss() {
    int nT = g_nT, nO = g_nO;
    int rowBase = blockIdx.x * 16;
    if (rowBase >= nT) return;
    int chunk = blockIdx.y;
    int warp = threadIdx.x >> 5, lane = threadIdx.x & 31;
    int r0 = rowBase + warp * 2;
    int r1 = r0 + 1;
    bool v0 = r0 < nT, v1 = r1 < nT;

    float4 tr0[8], tr1[8];
#pragma unroll
    for (int q = 0; q < 8; q++) { tr0[q] = make_float4(0, 0, 0, 0); tr1[q] = tr0[q]; }
    if (v0) { const float4* tp = (const float4*)(g_cols + r0 * CF);
#pragma unroll
        for (int q = 0; q < 8; q++) tr0[q] = tp[q]; }
    if (v1) { const float4* tp = (const float4*)(g_cols + r1 * CF);
#pragma unroll
        for (int q = 0; q < 8; q++) tr1[q] = tp[q]; }

    __shared__ float4 stile[128 * 9];   // [col][9] float4, 8 used + pad
    float mT0 = -1e30f, sT0 = 0.f, mO0 = -1e30f, sO0 = 0.f;
    float mT1 = -1e30f, sT1 = 0.f, mO1 = -1e30f, sO1 = 0.f;

    int chunkBase = chunk * 640;
    for (int tile = 0; tile < 5; tile++) {
        int cbase = chunkBase + tile * 128;
        __syncthreads();
        const float4* gc = (const float4*)g_cols;
#pragma unroll
        for (int i = threadIdx.x; i < 1024; i += 256) {
            int col = i >> 3, q = i & 7;
            stile[col * 9 + q] = gc[(cbase + col) * 8 + q];
        }
        __syncthreads();
#pragma unroll
        for (int cc = 0; cc < 4; cc++) {
            int j = cc * 32 + lane;
            int jc = cbase + j;
            bool isT = jc < nT;
            bool isO = (jc >= MAXT) && (jc < MAXT + nO);
            if (!(isT || isO)) continue;
            const float4* cp = &stile[j * 9];
            float d0 = 0.f, d1 = 0.f;
#pragma unroll
            for (int q = 0; q < 8; q++) {
                float4 c = cp[q];
                d0 += tr0[q].x * c.x + tr0[q].y * c.y + tr0[q].z * c.z + tr0[q].w * c.w;
                d1 += tr1[q].x * c.x + tr1[q].y * c.y + tr1[q].z * c.z + tr1[q].w * c.w;
            }
            float s0 = d0 * 10.0f;   // / TEMP
            float s1 = d1 * 10.0f;
            if (v0 && jc != r0) {
                if (isT) lseUpd(mT0, sT0, s0); else lseUpd(mO0, sO0, s0);
            }
            if (v1 && jc != r1) {
                if (isT) lseUpd(mT1, sT1, s1); else lseUpd(mO1, sO1, s1);
            }
        }
    }
    // warp merge (xor butterfly; all lanes converge)
#pragma unroll
    for (int o = 16; o; o >>= 1) {
        float m2, s2;
        m2 = __shfl_xor_sync(0xffffffffu, mT0, o); s2 = __shfl_xor_sync(0xffffffffu, sT0, o); lseMerge(mT0, sT0, m2, s2);
        m2 = __shfl_xor_sync(0xffffffffu, mO0, o); s2 = __shfl_xor_sync(0xffffffffu, sO0, o); lseMerge(mO0, sO0, m2, s2);
        m2 = __shfl_xor_sync(0xffffffffu, mT1, o); s2 = __shfl_xor_sync(0xffffffffu, sT1, o); lseMerge(mT1, sT1, m2, s2);
        m2 = __shfl_xor_sync(0xffffffffu, mO1, o); s2 = __shfl_xor_sync(0xffffffffu, sO1, o); lseMerge(mO1, sO1, m2, s2);
    }
    if (lane == 0) {
        if (v0) g_part[r0 * 8 + chunk] = make_float4(mT0, sT0, mO0, sO0);
        if (v1) g_part[r1 * 8 + chunk] = make_float4(mT1, sT1, mO1, sO1);
    }
}

// ---------------- pass 7: merge chunk LSEs -> tiny loss sum ----------------
__global__ void k_tinymerge() {
    int r = threadIdx.x;   // 1024 threads, 1 block
    if (r >= g_nT) return;
    float mN = -1e30f, sN = 0.f;
#pragma unroll
    for (int c = 0; c < 8; c++) { float4 q = g_part[r * 8 + c]; lseMerge(mN, sN, q.x, q.y); }
    float mD = mN, sD = sN;
#pragma unroll
    for (int c = 0; c < 8; c++) { float4 q = g_part[r * 8 + c]; lseMerge(mD, sD, q.z, q.w); }
    float per = (mD + logf(sD)) - (mN + logf(sN));
    atomicAdd(&g_tinySum, (double)per);
}

// ---------------- pass 8: class contrastive on embeddings (8x256) ----------------
__global__ __launch_bounds__(256) void k_cls(const float* __restrict__ emb,
                                             const int* __restrict__ lab) {
    __shared__ float e[Bsz * Dd];
    __shared__ float dotm[Bsz * Bsz];
    int t = threadIdx.x;
    for (int i = t; i < Bsz * Dd; i += 256) e[i] = emb[i];
    __syncthreads();
    int w = t >> 5, lane = t & 31;
    float sq = 0.f;
    for (int k = lane; k < Dd; k += 32) { float v = e[w * Dd + k]; sq += v * v; }
    WSUM(sq)
    float inv = 1.0f / fmaxf(sqrtf(sq), 1e-12f);
    for (int k = lane; k < Dd; k += 32) e[w * Dd + k] *= inv;
    __syncthreads();
    for (int j = 0; j < Bsz; j++) {
        float d = 0.f;
        for (int k = lane; k < Dd; k += 32) d += e[w * Dd + k] * e[j * Dd + k];
        WSUM(d)
        if (lane == 0) dotm[w * Bsz + j] = d;
    }
    __syncthreads();
    if (t == 0) {
        int L[Bsz];
        for (int i = 0; i < Bsz; i++) L[i] = lab[i];
        float per_sum = 0.f; int nvalid = 0;
        double bce_sum = 0.0;
        for (int i = 0; i < Bsz; i++) {
            float mP = -1e30f, sP = 0.f, mA = -1e30f, sA = 0.f;
            int has = 0;
            for (int j = 0; j < Bsz; j++) {
                if (j == i) continue;
                float dv = dotm[i * Bsz + j];
                float s = dv * 10.0f;   // / max(TEMP,1e-6)
                lseUpd(mA, sA, s);
                if (L[i] == L[j]) { has = 1; lseUpd(mP, sP, s); }
                float cosv = fminf(fmaxf(dv, -1.0f), 1.0f);
                float p01 = (cosv + 1.0f) * 0.5f;
                float l1 = fmaxf(logf(p01), -100.0f);
                float l2 = fmaxf(logf(1.0f - p01), -100.0f);
                float ts = (L[i] == L[j]) ? 1.0f : 0.0f;
                bce_sum += (double)(-(ts * l1 + (1.0f - ts) * l2));
            }
            if (has) {
                per_sum += (mA + logf(sA)) - (mP + logf(sP));
                nvalid++;
            }
        }
        float mainv = per_sum / (float)(nvalid > 0 ? nvalid : 1);
        float fb = (float)(bce_sum / 56.0);
        g_cls = (nvalid > 0) ? mainv : fb;
    }
}

// ---------------- pass 9: combine ----------------
__global__ void k_combine(float* __restrict__ out) {
    double N = (double)BHW;
    double ce = g_acc[0] / N;
    double fo = g_acc[1] / N;
    double gr = g_acc[17] / N;
    double ds = 0.0;
    for (int c = 0; c < Ccls; c++) {
        double inter = g_acc[7 + c];
        double den = g_acc[2 + c] + g_acc[12 + c];
        ds += (2.0 * inter + 1e-6) / (den + 1e-6);
    }
    double dice = 1.0 - ds / 5.0;
    double tiny = 0.0;
    if (g_enabled) {
        int n = g_nT > 0 ? g_nT : 1;
        tiny = g_tinySum / (double)n;
    }
    out[0] = (float)(ce + dice + fo + gr + tiny + (double)g_cls);
}

// ---------------- launch ----------------
extern "C" void kernel_launch(void* const* d_in, const int* in_sizes, int n_in,
                              void* d_out, int out_size) {
    const float* logits  = (const float*)d_in[0];
    const int*   targets = (const int*)d_in[1];
    const float* pf      = (const float*)d_in[2];
    const float* emb     = (const float*)d_in[3];
    const int*   clab    = (const int*)d_in[4];
    float* out = (float*)d_out;

    k_init<<<1, 32>>>();
    k_stats<<<NSCAN, 256>>>(logits, targets);
    k_sobel<<<BHW / 256, 256>>>(targets);
    k_scan<<<1, 1024>>>();
    k_scatter<<<NSCAN, 256>>>(targets);
    k_gather<<<(MAXT + MAXO) / 8, 256>>>(pf);
    k_tinyloss<<<dim3(64, 8), 256>>>();
    k_tinymerge<<<1, 1024>>>();
    k_cls<<<1, 256>>>(emb, clab);
    k_combine<<<1, 1>>>(out);
}

// round 2
// speedup vs baseline: 1.1792x; 1.1792x over previous
#include <cuda_runtime.h>

#define Bsz 8
#define Ccls 5
#define Hh 512
#define Ww 512
#define HW 262144      // 512*512
#define BHW 2097152    // 8*HW
#define CF 32
#define Dd 256
#define FG 1
#define MAXT 1024
#define MAXO 4096
#define NSCAN 2048     // 1024-px blocks
#define L2E 1.4426950408889634f
#define K10 14.426950408889634f   // 10 * log2(e)

// ---------------- scratch ----------------
__device__ double g_acc[18];        // 0 ce,1 focal,2..6 probsum,7..11 inter,12..16 cnt,17 grad
__device__ float  g_sb[NSCAN * 17]; // per-block partials from k_stats
__device__ float  g_predfg[BHW];
__device__ int    g_blockcnt[NSCAN];
__device__ int    g_blockpref[NSCAN];
__device__ int    g_flags[Bsz];
__device__ int    g_nT, g_nO, g_enabled;
__device__ int    g_tinyIdx[MAXT];
__device__ int    g_otherIdx[MAXO];
__device__ float  g_cols[(MAXT + MAXO) * CF];
__device__ float2 g_part2[MAXT * 8];   // {sumT, sumO} per (row, chunk)

#define WSUM(v) { _Pragma("unroll") for (int _o = 16; _o; _o >>= 1) v += __shfl_xor_sync(0xffffffffu, v, _o); }

// ---------------- pass 1: softmax stats ----------------
__global__ __launch_bounds__(256) void k_stats(const float* __restrict__ logits,
                                               const int* __restrict__ tgt) {
    int blk = blockIdx.x;
    int b = blk >> 8;
    int hwBase = (blk & 255) * 1024 + threadIdx.x * 4;
    const float* lb = logits + (size_t)b * Ccls * HW;

    float4 X[5];
#pragma unroll
    for (int c = 0; c < 5; c++) X[c] = *(const float4*)(lb + c * HW + hwBase);
    int4 tv = *(const int4*)(tgt + (size_t)b * HW + hwBase);
    int tA[4] = {tv.x, tv.y, tv.z, tv.w};

    float ceA = 0.f, foA = 0.f;
    float p0 = 0.f, p1 = 0.f, p2 = 0.f, p3 = 0.f, p4 = 0.f;
    float i0 = 0.f, i1 = 0.f, i2 = 0.f, i3 = 0.f, i4 = 0.f;
    float c0 = 0.f, c1 = 0.f, c2 = 0.f, c3 = 0.f, c4 = 0.f;
    int cntFG = 0;
    float pr[4];

#pragma unroll
    for (int k = 0; k < 4; k++) {
        float x0 = ((const float*)&X[0])[k], x1 = ((const float*)&X[1])[k],
              x2 = ((const float*)&X[2])[k], x3 = ((const float*)&X[3])[k],
              x4 = ((const float*)&X[4])[k];
        float m = fmaxf(fmaxf(fmaxf(x0, x1), fmaxf(x2, x3)), x4);
        float nm = -m * L2E;
        float e0 = exp2f(fmaf(x0, L2E, nm)), e1 = exp2f(fmaf(x1, L2E, nm)),
              e2 = exp2f(fmaf(x2, L2E, nm)), e3 = exp2f(fmaf(x3, L2E, nm)),
              e4 = exp2f(fmaf(x4, L2E, nm));
        float S = e0 + e1 + e2 + e3 + e4;
        float inv = __fdividef(1.0f, S);
        float logS = __logf(S);
        int t = tA[k];
        float xt = (t == 0) ? x0 : (t == 1) ? x1 : (t == 2) ? x2 : (t == 3) ? x3 : x4;
        float et = (t == 0) ? e0 : (t == 1) ? e1 : (t == 2) ? e2 : (t == 3) ? e3 : e4;
        float ce = (m - xt) + logS;
        float pt = et * inv;
        float om = 1.0f - pt;
        ceA += ce;
        foA = fmaf(om * om, ce, foA);
        p0 = fmaf(e0, inv, p0); p1 = fmaf(e1, inv, p1); p2 = fmaf(e2, inv, p2);
        p3 = fmaf(e3, inv, p3); p4 = fmaf(e4, inv, p4);
        if (t == 0) { i0 += pt; c0 += 1.f; }
        else if (t == 1) { i1 += pt; c1 += 1.f; cntFG++; }
        else if (t == 2) { i2 += pt; c2 += 1.f; }
        else if (t == 3) { i3 += pt; c3 += 1.f; }
        else { i4 += pt; c4 += 1.f; }
        pr[k] = e1 * inv;
    }
    *(float4*)(g_predfg + (size_t)b * HW + hwBase) = make_float4(pr[0], pr[1], pr[2], pr[3]);

    __shared__ float sa[17];
    __shared__ int scnt;
    if (threadIdx.x < 17) sa[threadIdx.x] = 0.f;
    if (threadIdx.x == 17) scnt = 0;
    __syncthreads();
    WSUM(ceA) WSUM(foA)
    WSUM(p0) WSUM(p1) WSUM(p2) WSUM(p3) WSUM(p4)
    WSUM(i0) WSUM(i1) WSUM(i2) WSUM(i3) WSUM(i4)
    WSUM(c0) WSUM(c1) WSUM(c2) WSUM(c3) WSUM(c4)
    WSUM(cntFG)
    if ((threadIdx.x & 31) == 0) {
        atomicAdd(&sa[0], ceA); atomicAdd(&sa[1], foA);
        atomicAdd(&sa[2], p0); atomicAdd(&sa[3], p1); atomicAdd(&sa[4], p2);
        atomicAdd(&sa[5], p3); atomicAdd(&sa[6], p4);
        atomicAdd(&sa[7], i0); atomicAdd(&sa[8], i1); atomicAdd(&sa[9], i2);
        atomicAdd(&sa[10], i3); atomicAdd(&sa[11], i4);
        atomicAdd(&sa[12], c0); atomicAdd(&sa[13], c1); atomicAdd(&sa[14], c2);
        atomicAdd(&sa[15], c3); atomicAdd(&sa[16], c4);
        atomicAdd(&scnt, cntFG);
    }
    __syncthreads();
    if (threadIdx.x < 17) g_sb[blk * 17 + threadIdx.x] = sa[threadIdx.x];
    if (threadIdx.x == 17) g_blockcnt[blk] = scnt;
}

// ---------------- pass 2: scan + reduce partials ----------------
__global__ __launch_bounds__(1024) void k_scan() {
    __shared__ int simg[Bsz], flg[Bsz], wsum[32];
    __shared__ float facc[17];
    int t = threadIdx.x, lane = t & 31, w = t >> 5;
    if (t < Bsz) simg[t] = 0;
    if (t < 17) facc[t] = 0.f;
    __syncthreads();

    int cA = g_blockcnt[2 * t], cB = g_blockcnt[2 * t + 1];
    int img = t >> 7;
    int pt = cA + cB;
    int ws = pt;
    WSUM(ws)
    if (lane == 0) atomicAdd(&simg[img], ws);

    // reduce stats partials: thread t handles blocks 2t, 2t+1
    float s17[17];
#pragma unroll
    for (int i = 0; i < 17; i++)
        s17[i] = g_sb[(2 * t) * 17 + i] + g_sb[(2 * t + 1) * 17 + i];
#pragma unroll
    for (int i = 0; i < 17; i++) { WSUM(s17[i]) }
    if (lane == 0) {
#pragma unroll
        for (int i = 0; i < 17; i++) atomicAdd(&facc[i], s17[i]);
    }
    __syncthreads();
    if (t < Bsz) flg[t] = (simg[t] > 0 && simg[t] <= 2048) ? 1 : 0;
    if (t < 17) g_acc[t] = (double)facc[t];
    if (t == 17) g_acc[17] = 0.0;   // sobel accumulates into this after us
    __syncthreads();

    int f = flg[img];
    int a0 = f ? cA : 0, a1 = f ? cB : 0, v = a0 + a1;
    int s = v;
#pragma unroll
    for (int off = 1; off < 32; off <<= 1) {
        int u = __shfl_up_sync(0xffffffffu, s, off);
        if (lane >= off) s += u;
    }
    if (lane == 31) wsum[w] = s;
    __syncthreads();
    int wbase = 0;
#pragma unroll
    for (int i = 0; i < 32; i++) wbase += (i < w) ? wsum[i] : 0;
    int excl = wbase + s - v;
    g_blockpref[2 * t] = excl;
    g_blockpref[2 * t + 1] = excl + a0;
    if (t < Bsz) g_flags[t] = flg[t];
    if (t == 1023) {
        int tot = wbase + s;
        g_nT = tot < MAXT ? tot : MAXT;
        int oth = BHW - tot;
        g_nO = oth < MAXO ? oth : MAXO;
        int any = flg[0] | flg[1] | flg[2] | flg[3] | flg[4] | flg[5] | flg[6] | flg[7];
        g_enabled = (any && tot >= 16) ? 1 : 0;
    }
}

// ---------------- pass 3: fused sobel + scatter ----------------
__global__ __launch_bounds__(256) void k_ss(const int* __restrict__ tgt) {
    __shared__ float spf[4][514];
    __shared__ float stf[4][514];
    __shared__ int wscan[8];
    __shared__ float sgrad;
    int sb = blockIdx.x;
    int b = sb >> 8;
    int r0 = (sb & 255) * 2;
    const float* pf = g_predfg + (size_t)b * HW;
    const int* tb = tgt + (size_t)b * HW;
    int t = threadIdx.x;

    if (t < 8) { spf[t & 3][(t < 4) ? 0 : 513] = 0.f; stf[t & 3][(t < 4) ? 0 : 513] = 0.f; }
    if (t == 8) sgrad = 0.f;
    {
        int lr = t >> 6;
        int c8 = (t & 63) * 8;
        int gr = r0 - 1 + lr;
        float4 pA = {0, 0, 0, 0}, pB = pA, fA = pA, fB = pA;
        if (gr >= 0 && gr < Hh) {
            const float4* prow = (const float4*)(pf + gr * Ww + c8);
            pA = prow[0]; pB = prow[1];
            const int4* trow = (const int4*)(tb + gr * Ww + c8);
            int4 u0 = trow[0], u1 = trow[1];
            fA = make_float4(u0.x > 0 ? 1.f : 0.f, u0.y > 0 ? 1.f : 0.f,
                             u0.z > 0 ? 1.f : 0.f, u0.w > 0 ? 1.f : 0.f);
            fB = make_float4(u1.x > 0 ? 1.f : 0.f, u1.y > 0 ? 1.f : 0.f,
                             u1.z > 0 ? 1.f : 0.f, u1.w > 0 ? 1.f : 0.f);
        }
        float* dp = &spf[lr][1 + c8];
        dp[0] = pA.x; dp[1] = pA.y; dp[2] = pA.z; dp[3] = pA.w;
        dp[4] = pB.x; dp[5] = pB.y; dp[6] = pB.z; dp[7] = pB.w;
        float* df = &stf[lr][1 + c8];
        df[0] = fA.x; df[1] = fA.y; df[2] = fA.z; df[3] = fA.w;
        df[4] = fB.x; df[5] = fB.y; df[6] = fB.z; df[7] = fB.w;
    }
    __syncthreads();

    // sobel on own 2 rows (4 px/thread)
    int local = t * 4;
    int lrow = 1 + (local >> 9);
    int col0 = local & 511;
    float dsum = 0.f;
#pragma unroll
    for (int k = 0; k < 4; k++) {
        int c = col0 + k + 1;
        float p00 = spf[lrow - 1][c - 1], p01 = spf[lrow - 1][c], p02 = spf[lrow - 1][c + 1];
        float p10 = spf[lrow][c - 1],                             p12 = spf[lrow][c + 1];
        float p20 = spf[lrow + 1][c - 1], p21 = spf[lrow + 1][c], p22 = spf[lrow + 1][c + 1];
        float gxp = (p02 + 2.f * p12 + p22) - (p00 + 2.f * p10 + p20);
        float gyp = (p20 + 2.f * p21 + p22) - (p00 + 2.f * p01 + p02);
        float q00 = stf[lrow - 1][c - 1], q01 = stf[lrow - 1][c], q02 = stf[lrow - 1][c + 1];
        float q10 = stf[lrow][c - 1],                             q12 = stf[lrow][c + 1];
        float q20 = stf[lrow + 1][c - 1], q21 = stf[lrow + 1][c], q22 = stf[lrow + 1][c + 1];
        float gxt = (q02 + 2.f * q12 + q22) - (q00 + 2.f * q10 + q20);
        float gyt = (q20 + 2.f * q21 + q22) - (q00 + 2.f * q01 + q02);
        float sp = sqrtf(fmaf(gxp, gxp, gyp * gyp) + 1e-6f);
        float st = sqrtf(fmaf(gxt, gxt, gyt * gyt) + 1e-6f);
        dsum += fabsf(sp - st);
    }
    WSUM(dsum)
    if ((t & 31) == 0) atomicAdd(&sgrad, dsum);

    // scatter of first-N indices
    int prefT = g_blockpref[sb];
    int prefO = sb * 1024 - prefT;
    int nT = g_nT, nO = g_nO;
    int flag = g_flags[b];
    int4 tv = *(const int4*)(tb + r0 * Ww + t * 4);
    int m0 = (tv.x == FG && flag) ? 1 : 0;
    int m1 = (tv.y == FG && flag) ? 1 : 0;
    int m2 = (tv.z == FG && flag) ? 1 : 0;
    int m3 = (tv.w == FG && flag) ? 1 : 0;
    int cnt = m0 + m1 + m2 + m3;
    int lane = t & 31, w = t >> 5;
    int s = cnt;
#pragma unroll
    for (int off = 1; off < 32; off <<= 1) {
        int u = __shfl_up_sync(0xffffffffu, s, off);
        if (lane >= off) s += u;
    }
    if (lane == 31) wscan[w] = s;
    __syncthreads();
    int wbase = 0;
#pragma unroll
    for (int i = 0; i < 8; i++) wbase += (i < w) ? wscan[i] : 0;
    int myExcl = wbase + s - cnt;
    if (prefT < nT || prefO < nO) {
        int tb2 = prefT + myExcl;
        int ob = prefO + t * 4 - myExcl;
        int p = sb * 1024 + t * 4;
        if (m0) { if (tb2 < nT) g_tinyIdx[tb2] = p; tb2++; } else { if (ob < nO) g_otherIdx[ob] = p; ob++; }
        p++;
        if (m1) { if (tb2 < nT) g_tinyIdx[tb2] = p; tb2++; } else { if (ob < nO) g_otherIdx[ob] = p; ob++; }
        p++;
        if (m2) { if (tb2 < nT) g_tinyIdx[tb2] = p; tb2++; } else { if (ob < nO) g_otherIdx[ob] = p; ob++; }
        p++;
        if (m3) { if (tb2 < nT) g_tinyIdx[tb2] = p; tb2++; } else { if (ob < nO) g_otherIdx[ob] = p; ob++; }
    }
    __syncthreads();
    if (t == 0) atomicAdd(&g_acc[17], (double)sgrad);
}

// ---------------- pass 4: gather + l2norm ----------------
__global__ __launch_bounds__(256) void k_gather(const float* __restrict__ pf) {
    int r = blockIdx.x * 8 + (threadIdx.x >> 5);
    int lane = threadIdx.x & 31;
    int nT = g_nT, nO = g_nO;
    int idx = -1;
    if (r < MAXT) { if (r < nT) idx = g_tinyIdx[r]; }
    else { int j = r - MAXT; if (j < nO) idx = g_otherIdx[j]; }
    float v = 0.f;
    if (idx >= 0) {
        int b = idx >> 18;
        int hw = idx & (HW - 1);
        v = pf[(size_t)(b * CF + lane) * HW + hw];
    }
    float sq = v * v;
    WSUM(sq)
    float nrm = fmaxf(sqrtf(sq), 1e-12f);
    g_cols[r * CF + lane] = v / nrm;   // invalid rows -> exact 0
}

// ---------------- pass 5: tiny contrastive, fixed-max exp sums ----------------
__global__ __launch_bounds__(256) void k_tinyloss() {
    int rowBase = blockIdx.x * 16;
    if (rowBase >= g_nT) return;
    int chunk = blockIdx.y;
    int warp = threadIdx.x >> 5, lane = threadIdx.x & 31;
    int r0 = rowBase + warp * 2;
    int r1 = r0 + 1;
    int nT = g_nT;
    bool v0 = r0 < nT, v1 = r1 < nT;

    float4 tr0[8], tr1[8];
#pragma unroll
    for (int q = 0; q < 8; q++) { tr0[q] = make_float4(0, 0, 0, 0); tr1[q] = tr0[q]; }
    if (v0) { const float4* tp = (const float4*)(g_cols + r0 * CF);
#pragma unroll
        for (int q = 0; q < 8; q++) tr0[q] = tp[q]; }
    if (v1) { const float4* tp = (const float4*)(g_cols + r1 * CF);
#pragma unroll
        for (int q = 0; q < 8; q++) tr1[q] = tp[q]; }

    __shared__ float4 stile[128 * 9];
    float sT0 = 0.f, sO0 = 0.f, sT1 = 0.f, sO1 = 0.f;
    int chunkBase = chunk * 640;

    for (int tile = 0; tile < 5; tile++) {
        int cbase = chunkBase + tile * 128;
        __syncthreads();
        const float4* gc = (const float4*)g_cols;
#pragma unroll
        for (int i = threadIdx.x; i < 1024; i += 256) {
            int col = i >> 3, q = i & 7;
            stile[col * 9 + q] = gc[(cbase + col) * 8 + q];
        }
        __syncthreads();
#pragma unroll
        for (int cc = 0; cc < 4; cc++) {
            int j = cc * 32 + lane;
            int jc = cbase + j;
            const float4* cp = &stile[j * 9];
            float d0 = 0.f, d1 = 0.f;
#pragma unroll
            for (int q = 0; q < 8; q++) {
                float4 c = cp[q];
                d0 = fmaf(tr0[q].x, c.x, d0); d0 = fmaf(tr0[q].y, c.y, d0);
                d0 = fmaf(tr0[q].z, c.z, d0); d0 = fmaf(tr0[q].w, c.w, d0);
                d1 = fmaf(tr1[q].x, c.x, d1); d1 = fmaf(tr1[q].y, c.y, d1);
                d1 = fmaf(tr1[q].z, c.z, d1); d1 = fmaf(tr1[q].w, c.w, d1);
            }
            float w0 = exp2f(fmaf(d0, K10, -K10));
            float w1 = exp2f(fmaf(d1, K10, -K10));
            if (jc < MAXT) { sT0 += w0; sT1 += w1; }   // warp-uniform branch
            else           { sO0 += w0; sO1 += w1; }
        }
    }
    WSUM(sT0) WSUM(sO0) WSUM(sT1) WSUM(sO1)
    if (lane == 0) {
        if (v0) g_part2[r0 * 8 + chunk] = make_float2(sT0, sO0);
        if (v1) g_part2[r1 * 8 + chunk] = make_float2(sT1, sO1);
    }
}

// ---------------- pass 6: final (tiny merge + cls contrastive + combine) ----------------
__global__ __launch_bounds__(1024) void k_final(const float* __restrict__ emb,
                                                const int* __restrict__ lab,
                                                float* __restrict__ out) {
    __shared__ float e[Bsz * Dd];
    __shared__ float dotm[Bsz * Bsz];
    __shared__ float red[32];
    int t = threadIdx.x, lane = t & 31, w = t >> 5;
    int nT = g_nT, nO = g_nO;

    float per = 0.f;
    if (t < nT) {
        float sT = 0.f, sO = 0.f;
#pragma unroll
        for (int c = 0; c < 8; c++) { float2 q = g_part2[t * 8 + c]; sT += q.x; sO += q.y; }
        const float c0 = exp2f(-K10);
        sT -= 1.0f + (float)(MAXT - nT) * c0;   // remove self + zero-padded cols
        sO -= (float)(MAXO - nO) * c0;
        sT = fmaxf(sT, 1e-30f);
        per = log1pf(sO / sT);
    }

    for (int i = t; i < Bsz * Dd; i += 1024) e[i] = emb[i];
    __syncthreads();
    if (t < 256) {
        float sq = 0.f;
        for (int k = lane; k < Dd; k += 32) { float v = e[w * Dd + k]; sq += v * v; }
        WSUM(sq)
        float inv = 1.0f / fmaxf(sqrtf(sq), 1e-12f);
        for (int k = lane; k < Dd; k += 32) e[w * Dd + k] *= inv;
    }
    __syncthreads();
    if (t < 256) {
        for (int j = 0; j < Bsz; j++) {
            float d = 0.f;
            for (int k = lane; k < Dd; k += 32) d += e[w * Dd + k] * e[j * Dd + k];
            WSUM(d)
            if (lane == 0) dotm[w * Bsz + j] = d;
        }
    }
    __syncthreads();

    WSUM(per)
    if (lane == 0) red[w] = per;
    __syncthreads();

    if (t == 0) {
        float tinySum = 0.f;
        for (int i = 0; i < 32; i++) tinySum += red[i];

        int L[Bsz];
        for (int i = 0; i < Bsz; i++) L[i] = lab[i];
        float per_sum = 0.f; int nvalid = 0;
        double bce_sum = 0.0;
        for (int i = 0; i < Bsz; i++) {
            float sP = 0.f, sA = 0.f; int has = 0;
            for (int j = 0; j < Bsz; j++) {
                if (j == i) continue;
                float dv = dotm[i * Bsz + j];
                float wE = exp2f(fmaf(dv, K10, -K10));
                sA += wE;
                if (L[i] == L[j]) { has = 1; sP += wE; }
                float cosv = fminf(fmaxf(dv, -1.0f), 1.0f);
                float p01 = (cosv + 1.0f) * 0.5f;
                float l1 = fmaxf(logf(p01), -100.0f);
                float l2 = fmaxf(logf(1.0f - p01), -100.0f);
                float ts = (L[i] == L[j]) ? 1.0f : 0.0f;
                bce_sum += (double)(-(ts * l1 + (1.0f - ts) * l2));
            }
            if (has) { per_sum += logf(sA / sP); nvalid++; }
        }
        float clsv = (nvalid > 0) ? per_sum / (float)nvalid : (float)(bce_sum / 56.0);

        double N = (double)BHW;
        double ce = g_acc[0] / N;
        double fo = g_acc[1] / N;
        double gr = g_acc[17] / N;
        double ds = 0.0;
        for (int c = 0; c < Ccls; c++) {
            double inter = g_acc[7 + c];
            double den = g_acc[2 + c] + g_acc[12 + c];
            ds += (2.0 * inter + 1e-6) / (den + 1e-6);
        }
        double dice = 1.0 - ds / 5.0;
        double tiny = 0.0;
        if (g_enabled) tiny = (double)tinySum / (double)(nT > 0 ? nT : 1);
        out[0] = (float)(ce + dice + fo + gr + tiny + (double)clsv);
    }
}

// ---------------- launch ----------------
extern "C" void kernel_launch(void* const* d_in, const int* in_sizes, int n_in,
                              void* d_out, int out_size) {
    const float* logits  = (const float*)d_in[0];
    const int*   targets = (const int*)d_in[1];
    const float* pf      = (const float*)d_in[2];
    const float* emb     = (const float*)d_in[3];
    const int*   clab    = (const int*)d_in[4];
    float* out = (float*)d_out;

    k_stats<<<NSCAN, 256>>>(logits, targets);
    k_scan<<<1, 1024>>>();
    k_ss<<<NSCAN, 256>>>(targets);
    k_gather<<<(MAXT + MAXO) / 8, 256>>>(pf);
    k_tinyloss<<<dim3(64, 8), 256>>>();
    k_final<<<1, 1024>>>(emb, clab, out);
}